// round 1
// baseline (speedup 1.0000x reference)
#include <cuda_runtime.h>
#include <cuda_bf16.h>

// Problem constants
#define BB  2
#define NN  16384
#define MM  4096
#define C1_ 128
#define C2_ 256
#define H1_ 256
#define H2_ 128

// ---------------------------------------------------------------------------
// Scratch (device globals — no runtime allocation allowed)
// ---------------------------------------------------------------------------
__device__ int3   g_idx[BB * NN];
__device__ float3 g_wts[BB * NN];
__device__ float  g_Gt[(size_t)BB * MM * H1_];          // (B, M, H1) point-major
__device__ float  g_Ut[(size_t)BB * NN * H1_];          // (B, N, H1) point-major
__device__ float  g_h [(size_t)BB * H1_ * NN];          // (B, H1, N) channel-major

// ---------------------------------------------------------------------------
// Kernel 1: brute-force 3-NN + inverse-distance weights
// One thread per query point; known points staged in shared memory (48KB).
// ---------------------------------------------------------------------------
__global__ void knn_kernel(const float* __restrict__ unknown,
                           const float* __restrict__ known,
                           int3* __restrict__ idx_out,
                           float3* __restrict__ wts_out)
{
    __shared__ float3 skn[MM];   // 4096 * 12B = 49152B
    const int b = blockIdx.y;

    const float3* kn = (const float3*)known + (size_t)b * MM;
    for (int i = threadIdx.x; i < MM; i += blockDim.x) skn[i] = kn[i];
    __syncthreads();

    const int n = blockIdx.x * blockDim.x + threadIdx.x;
    const float3 p = ((const float3*)unknown)[(size_t)b * NN + n];

    float d0 = 1e30f, d1 = 1e30f, d2 = 1e30f;
    int   i0 = 0, i1 = 0, i2 = 0;

    #pragma unroll 4
    for (int m = 0; m < MM; m++) {
        float dx = skn[m].x - p.x;
        float dy = skn[m].y - p.y;
        float dz = skn[m].z - p.z;
        float d  = dx * dx + dy * dy + dz * dz;
        if (d < d2) {
            if (d < d1) {
                if (d < d0) { d2 = d1; i2 = i1; d1 = d0; i1 = i0; d0 = d; i0 = m; }
                else        { d2 = d1; i2 = i1; d1 = d;  i1 = m; }
            } else          { d2 = d;  i2 = m; }
        }
    }

    float r0 = 1.0f / (sqrtf(d0) + 1e-8f);
    float r1 = 1.0f / (sqrtf(d1) + 1e-8f);
    float r2 = 1.0f / (sqrtf(d2) + 1e-8f);
    float rs = 1.0f / (r0 + r1 + r2);

    idx_out[(size_t)b * NN + n] = make_int3(i0, i1, i2);
    wts_out[(size_t)b * NN + n] = make_float3(r0 * rs, r1 * rs, r2 * rs);
}

// ---------------------------------------------------------------------------
// Register-tiled SGEMM: C = W(O,K; ldW) @ X(K,P)  [per batch z]
//   STORE_PO = true  -> C stored (P, O) point-major   (for Gt / Ut)
//   STORE_PO = false -> C stored (O, P) channel-major (final output)
//   RELU_BIAS: epilogue v = max(v + bias[o], 0)
// Tile 64x64x16, 256 threads, 4x4 per thread.
// ---------------------------------------------------------------------------
template <bool STORE_PO, bool RELU_BIAS>
__global__ void sgemm_kernel(const float* __restrict__ Wm, int ldW,
                             const float* __restrict__ X, long strideX,
                             float* __restrict__ C, long strideC,
                             const float* __restrict__ bias,
                             int O, int P, int K)
{
    constexpr int BO = 64, BP = 64, BK = 16;
    __shared__ float Ws[BK][BO];
    __shared__ float Xs[BK][BP];

    const float* Xb = X + (long)blockIdx.z * strideX;
    float*       Cb = C + (long)blockIdx.z * strideC;

    const int o0 = blockIdx.y * BO;
    const int p0 = blockIdx.x * BP;
    const int t  = threadIdx.x;
    const int tx = t & 15;          // P direction
    const int ty = t >> 4;          // O direction

    const int wo = t >> 2, wk = (t & 3) * 4;    // W tile load mapping
    const int xk = t >> 4, xp = (t & 15) * 4;   // X tile load mapping

    float acc[4][4] = {};

    for (int k0 = 0; k0 < K; k0 += BK) {
        float4 wv = *(const float4*)&Wm[(long)(o0 + wo) * ldW + k0 + wk];
        float4 xv = *(const float4*)&Xb[(long)(k0 + xk) * P + p0 + xp];

        Ws[wk + 0][wo] = wv.x;
        Ws[wk + 1][wo] = wv.y;
        Ws[wk + 2][wo] = wv.z;
        Ws[wk + 3][wo] = wv.w;
        *(float4*)&Xs[xk][xp] = xv;
        __syncthreads();

        #pragma unroll
        for (int k = 0; k < BK; k++) {
            float4 a  = *(const float4*)&Ws[k][ty * 4];
            float4 x4 = *(const float4*)&Xs[k][tx * 4];
            acc[0][0] += a.x * x4.x; acc[0][1] += a.x * x4.y;
            acc[0][2] += a.x * x4.z; acc[0][3] += a.x * x4.w;
            acc[1][0] += a.y * x4.x; acc[1][1] += a.y * x4.y;
            acc[1][2] += a.y * x4.z; acc[1][3] += a.y * x4.w;
            acc[2][0] += a.z * x4.x; acc[2][1] += a.z * x4.y;
            acc[2][2] += a.z * x4.z; acc[2][3] += a.z * x4.w;
            acc[3][0] += a.w * x4.x; acc[3][1] += a.w * x4.y;
            acc[3][2] += a.w * x4.z; acc[3][3] += a.w * x4.w;
        }
        __syncthreads();
    }

    const int ot = o0 + ty * 4;
    const int pt = p0 + tx * 4;

    if (RELU_BIAS) {
        #pragma unroll
        for (int i = 0; i < 4; i++) {
            float bi = bias[ot + i];
            #pragma unroll
            for (int j = 0; j < 4; j++)
                acc[i][j] = fmaxf(acc[i][j] + bi, 0.0f);
        }
    }

    if (STORE_PO) {
        #pragma unroll
        for (int j = 0; j < 4; j++) {
            float4 v = make_float4(acc[0][j], acc[1][j], acc[2][j], acc[3][j]);
            *(float4*)&Cb[(long)(pt + j) * O + ot] = v;
        }
    } else {
        #pragma unroll
        for (int i = 0; i < 4; i++) {
            float4 v = make_float4(acc[i][0], acc[i][1], acc[i][2], acc[i][3]);
            *(float4*)&Cb[(long)(ot + i) * P + pt] = v;
        }
    }
}

// ---------------------------------------------------------------------------
// Kernel 4: combine — h[b,o,n] = relu( sum_j w_j * Gt[b, idx_j, o] + Ut[b,n,o] + b1[o] )
// Warp per point (coalesced 1KB row gathers), 32 points per block,
// shared-memory transpose so the (H1, N) store is coalesced.
// ---------------------------------------------------------------------------
__global__ void combine_kernel(const float* __restrict__ Gt,
                               const float* __restrict__ Ut,
                               const int3* __restrict__ idx,
                               const float3* __restrict__ wts,
                               const float* __restrict__ b1,
                               float* __restrict__ h)
{
    __shared__ float smh[H1_][33];

    const int b    = blockIdx.y;
    const int n0   = blockIdx.x * 32;
    const int t    = threadIdx.x;
    const int warp = t >> 5;
    const int lane = t & 31;
    const int n    = n0 + warp;

    const int3   id = idx[(size_t)b * NN + n];
    const float3 ww = wts[(size_t)b * NN + n];

    const float* g0 = Gt + ((long)b * MM + id.x) * H1_;
    const float* g1 = Gt + ((long)b * MM + id.y) * H1_;
    const float* g2 = Gt + ((long)b * MM + id.z) * H1_;
    const float* ut = Ut + ((long)b * NN + n) * H1_;

    #pragma unroll
    for (int rep = 0; rep < 2; rep++) {
        int q = rep * 128 + lane * 4;
        float4 a  = *(const float4*)&g0[q];
        float4 bb = *(const float4*)&g1[q];
        float4 c  = *(const float4*)&g2[q];
        float4 u  = *(const float4*)&ut[q];
        float4 bv = *(const float4*)&b1[q];
        smh[q + 0][warp] = fmaxf(ww.x * a.x + ww.y * bb.x + ww.z * c.x + u.x + bv.x, 0.0f);
        smh[q + 1][warp] = fmaxf(ww.x * a.y + ww.y * bb.y + ww.z * c.y + u.y + bv.y, 0.0f);
        smh[q + 2][warp] = fmaxf(ww.x * a.z + ww.y * bb.z + ww.z * c.z + u.z + bv.z, 0.0f);
        smh[q + 3][warp] = fmaxf(ww.x * a.w + ww.y * bb.w + ww.z * c.w + u.w + bv.w, 0.0f);
    }
    __syncthreads();

    // 1024 threads write 256 rows x 32 cols, coalesced per row segment
    #pragma unroll
    for (int rep = 0; rep < 8; rep++) {
        int o = rep * 32 + warp;
        h[((long)b * H1_ + o) * NN + n0 + lane] = smh[o][lane];
    }
}

// ---------------------------------------------------------------------------
// Launch
// Inputs (metadata order): unknown, known, unknow_feats, known_feats, W1, b1, W2, b2
// Output: (B, H2, N) float32
// ---------------------------------------------------------------------------
extern "C" void kernel_launch(void* const* d_in, const int* in_sizes, int n_in,
                              void* d_out, int out_size)
{
    const float* unknown      = (const float*)d_in[0];
    const float* known        = (const float*)d_in[1];
    const float* unknow_feats = (const float*)d_in[2];
    const float* known_feats  = (const float*)d_in[3];
    const float* W1           = (const float*)d_in[4];
    const float* b1           = (const float*)d_in[5];
    const float* W2           = (const float*)d_in[6];
    const float* b2           = (const float*)d_in[7];
    float* out = (float*)d_out;

    void *pGt, *pUt, *pH, *pIdx, *pWts;
    cudaGetSymbolAddress(&pGt,  g_Gt);
    cudaGetSymbolAddress(&pUt,  g_Ut);
    cudaGetSymbolAddress(&pH,   g_h);
    cudaGetSymbolAddress(&pIdx, g_idx);
    cudaGetSymbolAddress(&pWts, g_wts);

    // 1) 3-NN + weights
    knn_kernel<<<dim3(NN / 256, BB), 256>>>(unknown, known, (int3*)pIdx, (float3*)pWts);

    // 2) Gt[b,m,o] = sum_c W1[o, c] * known_feats[b, c, m]   (c in [0,256): interpolated part)
    sgemm_kernel<true, false><<<dim3(MM / 64, H1_ / 64, BB), 256>>>(
        W1, C1_ + C2_, known_feats, (long)C2_ * MM,
        (float*)pGt, (long)MM * H1_, nullptr, H1_, MM, C2_);

    // 3) Ut[b,n,o] = sum_c W1[o, 256 + c] * unknow_feats[b, c, n]
    sgemm_kernel<true, false><<<dim3(NN / 64, H1_ / 64, BB), 256>>>(
        W1 + C2_, C1_ + C2_, unknow_feats, (long)C1_ * NN,
        (float*)pUt, (long)NN * H1_, nullptr, H1_, NN, C1_);

    // 4) h = relu(gathered-weighted Gt + Ut + b1), stored (B, H1, N)
    combine_kernel<<<dim3(NN / 32, BB), 1024>>>(
        (const float*)pGt, (const float*)pUt, (const int3*)pIdx,
        (const float3*)pWts, b1, (float*)pH);

    // 5) out = relu(W2 @ h + b2), stored (B, H2, N)
    sgemm_kernel<false, true><<<dim3(NN / 64, H2_ / 64, BB), 256>>>(
        W2, H1_, (const float*)pH, (long)H1_ * NN,
        out, (long)H2_ * NN, b2, H2_, NN, H1_);
}